// round 2
// baseline (speedup 1.0000x reference)
#include <cuda_runtime.h>
#include <math.h>

#ifndef M_PI
#define M_PI 3.14159265358979323846
#endif

// Scratch for deterministic two-pass reduction (no device allocation allowed).
__device__ double g_partials[4096];

__device__ __forceinline__ float sgnf(float a) { return a > 0.0f ? 1.0f : -1.0f; }

// Faithful float32 replication of reference cordicII_ang + 1.57*sin(.)
__device__ __forceinline__ float cordic_est(float theta) {
    const float TWO_PI_F  = (float)(2.0 * M_PI);
    const float PI_F      = (float)M_PI;
    const float PI_3_4_F  = (float)(3.0 * M_PI / 4.0);
    const float PI_1_4_F  = (float)(M_PI / 4.0);
    const float PI_1_2_F  = (float)(M_PI / 2.0);
    const float D3_5      = (float)(3.5 * M_PI / 180.0);
    const float D7_125    = (float)(7.125 * M_PI / 180.0);
    const float D8_13     = (float)((16.26 / 2.0) * M_PI / 180.0);
    const float D26_565   = (float)(((36.87 + 16.26) / 2.0) * M_PI / 180.0);
    const float D16_26    = (float)(16.26 * M_PI / 180.0);
    const float D36_87    = (float)(36.87 * M_PI / 180.0);

    // trivial_rotation
    float t = fmodf(theta, TWO_PI_F);
    t = (fabsf(t) > PI_F) ? (t - sgnf(t) * TWO_PI_F) : t;
    float at = fabsf(t);
    float rotmag = (at > PI_3_4_F) ? PI_F : ((at > PI_1_4_F) ? PI_1_2_F : 0.0f);
    float r = t - sgnf(t) * rotmag;
    // friend_angles
    float s  = sgnf(r);
    float ar = fabsf(r);
    r = (ar < D8_13) ? r : ((ar < D26_565) ? (r - s * D16_26) : (r - s * D36_87));
    // USRcordic
    ar = fabsf(r);
    float step = (r > 0.0f) ? -D7_125 : D7_125;
    r = (ar < D3_5) ? r : (r + step);
    // ests = 1.57 * sin(theta - r)
    return 1.57f * sinf(theta - r);
}

__global__ void __launch_bounds__(256) rope_dot_kernel(
    const float4* __restrict__ vec4,
    const float4* __restrict__ th4,
    const int*    __restrict__ m_ptr,
    int n4)
{
    const float m = (float)(*m_ptr);
    double acc = 0.0;
    const int stride = gridDim.x * blockDim.x;
    for (int i = blockIdx.x * blockDim.x + threadIdx.x; i < n4; i += stride) {
        float4 v = __ldg(&vec4[i]);
        float4 t = __ldg(&th4[i]);
        // pairs (4i,4i+1) and (4i+2,4i+3): ests identical within a pair,
        // total contribution per pair = 2 * e * v[even]
        float e0 = cordic_est(m * t.x);
        float e1 = cordic_est(m * t.z);
        acc += (double)e0 * (double)v.x + (double)e1 * (double)v.z;
    }

    // intra-warp reduce
    #pragma unroll
    for (int off = 16; off > 0; off >>= 1)
        acc += __shfl_down_sync(0xffffffffu, acc, off);

    __shared__ double sh[8];
    int lane = threadIdx.x & 31;
    int w    = threadIdx.x >> 5;
    if (lane == 0) sh[w] = acc;
    __syncthreads();
    if (w == 0) {
        double a = (lane < 8) ? sh[lane] : 0.0;
        #pragma unroll
        for (int off = 4; off > 0; off >>= 1)
            a += __shfl_down_sync(0xffffffffu, a, off);
        if (lane == 0) g_partials[blockIdx.x] = 2.0 * a;  // factor 2 from pair identity
    }
}

__global__ void __launch_bounds__(1024) final_reduce_kernel(float* out, int nparts) {
    double a = 0.0;
    for (int i = threadIdx.x; i < nparts; i += blockDim.x)
        a += g_partials[i];
    #pragma unroll
    for (int off = 16; off > 0; off >>= 1)
        a += __shfl_down_sync(0xffffffffu, a, off);

    __shared__ double sh[32];
    int lane = threadIdx.x & 31;
    int w    = threadIdx.x >> 5;
    if (lane == 0) sh[w] = a;
    __syncthreads();
    if (w == 0) {
        a = (lane < 32) ? sh[lane] : 0.0;
        #pragma unroll
        for (int off = 16; off > 0; off >>= 1)
            a += __shfl_down_sync(0xffffffffu, a, off);
        if (lane == 0) out[0] = (float)a;
    }
}

extern "C" void kernel_launch(void* const* d_in, const int* in_sizes, int n_in,
                              void* d_out, int out_size) {
    const float4* vec4 = (const float4*)d_in[0];
    const float4* th4  = (const float4*)d_in[1];
    const int*    mptr = (const int*)d_in[2];

    int n  = in_sizes[0];
    int n4 = n / 4;

    const int threads = 256;
    const int blocks  = 1184;  // 148 SMs * 8 CTAs -> full occupancy, grid-stride

    rope_dot_kernel<<<blocks, threads>>>(vec4, th4, mptr, n4);
    final_reduce_kernel<<<1, 1024>>>((float*)d_out, blocks);
}

// round 3
// speedup vs baseline: 1.8221x; 1.8221x over previous
#include <cuda_runtime.h>
#include <math.h>

// ---------------------------------------------------------------------------
// ROPE_64252710748794: out = ests @ vec + ests @ neg_swapped(vec)
// Since repeated_thetas pairs are bitwise equal, ests[2k]==ests[2k+1]=e_k and
// the whole thing collapses to  2 * sum_k e_k * vec[2k],  e_k = 1.57*sin(C_k)
// where C_k is the discretely-applied CORDIC rotation. We evaluate sin via
// exact compile-time constants + angle addition (no sinf, no fmodf, no FP64
// in the hot loop).
// ---------------------------------------------------------------------------

// f32-exact constants (literals round to the same f32 values the reference uses)
#define TWO_PI_F   6.283185307179586f     // rounds to f32(2*pi) = 6.28318548...
#define PI_F       3.141592653589793f     // f32(pi)
#define PI_12_F    1.5707963267948966f    // f32(pi/2)
#define PI_34_F    2.356194490192345f     // f32(3*pi/4)
#define PI_14_F    0.7853981633974483f    // f32(pi/4)
#define INV2PI_F   0.15915494309189535f
// 2*pi(f32) - 2*pi(exact): fold-count phase drift per 2pi
#define DELTA_F    1.7484556000744818e-7f

// thresholds (radians of the degree literals, double->f32)
#define D3_5_F     0.061086523819801536f
#define D8_13_F    0.14189526818745917f   // radians(16.26/2)
#define D26_565_F  0.46364671567952505f   // radians((36.87+16.26)/2)
#define D16_26_F   0.28379053637491834f
#define D36_87_F   0.64350289521467380f

// exact sin/cos of friend + micro angles (computed in double precision)
#define SIN_F1_F   0.27999656988459544f   // sin(16.26 deg)
#define COS_F1_F   0.96000100046478220f   // cos(16.26 deg)
#define SIN_F2_F   0.60000142963530880f   // sin(36.87 deg)
#define COS_F2_F   0.79999892777837827f   // cos(36.87 deg)
#define SIN_U_F    0.12403445401859652f   // sin(7.125 deg)
#define COS_U_F    0.99227790841661646f   // cos(7.125 deg)

__device__ float        g_partials[4096];
__device__ unsigned int g_ticket;

// sin(theta - r) for the reference cordicII pipeline, via discrete rotations.
__device__ __forceinline__ float est_sin(float th, float m) {
    float theta = m * th;                          // m = 4096 (pow2): exact
    // exact fmod(theta, 2pi_f32): fma reproduces the exactly-representable
    // remainder in one rounding; fix quotient off-by-one.
    float fn = floorf(theta * INV2PI_F);
    float t0 = fmaf(-fn, TWO_PI_F, theta);
    if (t0 < 0.0f)       { t0 += TWO_PI_F; fn -= 1.0f; }
    if (t0 >= TWO_PI_F)  { t0 -= TWO_PI_F; fn += 1.0f; }

    // fold into (-pi, pi] (Sterbenz-exact subtraction, matches reference)
    bool  fold = t0 > PI_F;
    float t    = fold ? (t0 - TWO_PI_F) : t0;
    float neff = fold ? (fn + 1.0f)     : fn;

    // quadrant rotation Q = sgn(t) * rotmag
    float at   = fabsf(t);
    float sgnt = (t > 0.0f) ? 1.0f : -1.0f;
    bool  q2   = at > PI_34_F;
    bool  q1   = at > PI_14_F;
    float rot  = q2 ? PI_F : (q1 ? PI_12_F : 0.0f);
    float r    = t - sgnt * rot;                   // exact mul (+-1 * const)

    // friend rotation s*F
    float s  = (r > 0.0f) ? 1.0f : -1.0f;
    float ar = fabsf(r);
    bool  f2 = ar >= D26_565_F;
    bool  f1 = ar >= D8_13_F;
    float sinF = f2 ? SIN_F2_F : (f1 ? SIN_F1_F : 0.0f);
    float cosF = f2 ? COS_F2_F : (f1 ? COS_F1_F : 1.0f);
    float Fv   = f2 ? D36_87_F : (f1 ? D16_26_F : 0.0f);
    float r2   = r - s * Fv;

    // micro rotation u = sgn(r2)*7.125deg if |r2| >= 3.5deg  (u = -step)
    bool  um   = fabsf(r2) >= D3_5_F;
    float su   = (r2 > 0.0f) ? 1.0f : -1.0f;
    float sinU = um ? su * SIN_U_F : 0.0f;
    float cosU = um ? COS_U_F      : 1.0f;

    // c = s*F + u   ->   sin(c), cos(c) by angle addition
    float sSinF = s * sinF;                        // exact
    float sc = fmaf(sSinF, cosU,  cosF * sinU);    // sin(c)
    float cc = fmaf(cosF,  cosU, -sSinF * sinU);   // cos(c)

    // C = Q + c : combine with quadrant (sinQ,cosQ in {0,+-1})
    float sinC, cosC;
    if (q2)      { sinC = -sc;        cosC = -cc;        }  // Q = +-pi
    else if (q1) { sinC = sgnt * cc;  cosC = -sgnt * sc; }  // Q = sgn*pi/2
    else         { sinC = sc;         cosC = cc;         }

    // phase drift from reducing by 2pi_f32 instead of 2pi: + neff*DELTA
    return fmaf(cosC, neff * DELTA_F, sinC);
}

__global__ void __launch_bounds__(256) rope_dot_kernel(
    const float4* __restrict__ vec4,
    const float4* __restrict__ th4,
    const int*    __restrict__ m_ptr,
    float*        __restrict__ out,
    int n4)
{
    const float m = (float)(*m_ptr);
    float acc0 = 0.0f, acc1 = 0.0f;
    const int stride = gridDim.x * blockDim.x;

    #pragma unroll 4
    for (int i = blockIdx.x * blockDim.x + threadIdx.x; i < n4; i += stride) {
        float4 v = __ldg(&vec4[i]);
        float4 t = __ldg(&th4[i]);
        // pairs (4i,4i+1) and (4i+2,4i+3): e identical within a pair
        acc0 = fmaf(est_sin(t.x, m), v.x, acc0);
        acc1 = fmaf(est_sin(t.z, m), v.z, acc1);
    }
    float acc = acc0 + acc1;

    // intra-warp reduce (f32)
    #pragma unroll
    for (int off = 16; off > 0; off >>= 1)
        acc += __shfl_down_sync(0xffffffffu, acc, off);

    __shared__ float sh[8];
    __shared__ bool  is_last;
    int lane = threadIdx.x & 31;
    int w    = threadIdx.x >> 5;
    if (lane == 0) sh[w] = acc;
    __syncthreads();
    if (threadIdx.x == 0) {
        float b = sh[0];
        #pragma unroll
        for (int k = 1; k < 8; k++) b += sh[k];
        g_partials[blockIdx.x] = b;
        __threadfence();
        unsigned tk = atomicAdd(&g_ticket, 1u);
        is_last = (tk == gridDim.x - 1);
    }
    __syncthreads();

    if (is_last) {
        // final deterministic reduction (double, tiny op count)
        double a = 0.0;
        for (int i = threadIdx.x; i < gridDim.x; i += blockDim.x)
            a += (double)g_partials[i];
        #pragma unroll
        for (int off = 16; off > 0; off >>= 1)
            a += __shfl_down_sync(0xffffffffu, a, off);
        __shared__ double shd[8];
        if (lane == 0) shd[w] = a;
        __syncthreads();
        if (threadIdx.x == 0) {
            double tot = shd[0];
            #pragma unroll
            for (int k = 1; k < 8; k++) tot += shd[k];
            // factor 2 (pair identity) * 1.57 (reference scale)
            out[0] = (float)(tot * (2.0 * (double)1.57f));
            g_ticket = 0;  // reset for next graph replay
        }
    }
}

extern "C" void kernel_launch(void* const* d_in, const int* in_sizes, int n_in,
                              void* d_out, int out_size) {
    const float4* vec4 = (const float4*)d_in[0];
    const float4* th4  = (const float4*)d_in[1];
    const int*    mptr = (const int*)d_in[2];

    int n  = in_sizes[0];
    int n4 = n / 4;

    const int threads = 256;
    const int blocks  = 592;   // 148 SMs * 4 CTAs: single wave, grid-stride

    rope_dot_kernel<<<blocks, threads>>>(vec4, th4, mptr, (float*)d_out, n4);
}

// round 4
// speedup vs baseline: 2.1423x; 1.1757x over previous
#include <cuda_runtime.h>
#include <math.h>

// ---------------------------------------------------------------------------
// ROPE_64252710748794: out = ests @ vec + ests @ neg_swapped(vec)
// repeated_thetas pairs are bitwise equal => ests[2k]==ests[2k+1]=e_k and the
// result collapses to 2 * sum_k e_k * vec[2k], e_k = 1.57*sin(C_k) with C_k
// the discretely-applied CORDIC rotation (exact-constant angle addition; no
// sinf/fmodf/FP64 in the hot loop).
// Round 4: 8 CTAs/SM (2048 thr/SM) — round 3 ran at 50% occupancy cap.
// ---------------------------------------------------------------------------

#define TWO_PI_F   6.283185307179586f
#define PI_F       3.141592653589793f
#define PI_12_F    1.5707963267948966f
#define PI_34_F    2.356194490192345f
#define PI_14_F    0.7853981633974483f
#define INV2PI_F   0.15915494309189535f
#define DELTA_F    1.7484556000744818e-7f   // f32(2pi) - 2pi

#define D3_5_F     0.061086523819801536f
#define D8_13_F    0.14189526818745917f
#define D26_565_F  0.46364671567952505f
#define D16_26_F   0.28379053637491834f
#define D36_87_F   0.64350289521467380f

#define SIN_F1_F   0.27999656988459544f
#define COS_F1_F   0.96000100046478220f
#define SIN_F2_F   0.60000142963530880f
#define COS_F2_F   0.79999892777837827f
#define SIN_U_F    0.12403445401859652f
#define COS_U_F    0.99227790841661646f

__device__ float        g_partials[4096];
__device__ unsigned int g_ticket;

// sin(theta - r) for the reference cordicII pipeline via discrete rotations.
__device__ __forceinline__ float est_sin(float th, float m) {
    float theta = m * th;                    // m = 4096 (pow2): exact scale
    // exact fmod(theta, 2pi_f32) via single-rounding FMA + off-by-one fixups
    float fn = floorf(theta * INV2PI_F);
    float t0 = fmaf(-fn, TWO_PI_F, theta);
    if (t0 < 0.0f)       { t0 += TWO_PI_F; fn -= 1.0f; }
    if (t0 >= TWO_PI_F)  { t0 -= TWO_PI_F; fn += 1.0f; }

    // fold into (-pi, pi]
    bool  fold = t0 > PI_F;
    float t    = fold ? (t0 - TWO_PI_F) : t0;
    float neff = fold ? (fn + 1.0f)     : fn;

    // quadrant rotation
    float at   = fabsf(t);
    float sgnt = (t > 0.0f) ? 1.0f : -1.0f;
    bool  q2   = at > PI_34_F;
    bool  q1   = at > PI_14_F;
    float rot  = q2 ? PI_F : (q1 ? PI_12_F : 0.0f);
    float r    = t - sgnt * rot;

    // friend rotation
    float s  = (r > 0.0f) ? 1.0f : -1.0f;
    float ar = fabsf(r);
    bool  f2 = ar >= D26_565_F;
    bool  f1 = ar >= D8_13_F;
    float sinF = f2 ? SIN_F2_F : (f1 ? SIN_F1_F : 0.0f);
    float cosF = f2 ? COS_F2_F : (f1 ? COS_F1_F : 1.0f);
    float Fv   = f2 ? D36_87_F : (f1 ? D16_26_F : 0.0f);
    float r2   = r - s * Fv;

    // micro rotation
    bool  um   = fabsf(r2) >= D3_5_F;
    float su   = (r2 > 0.0f) ? 1.0f : -1.0f;
    float sinU = um ? su * SIN_U_F : 0.0f;
    float cosU = um ? COS_U_F      : 1.0f;

    // angle addition: c = s*F + u
    float sSinF = s * sinF;
    float sc = fmaf(sSinF, cosU,  cosF * sinU);
    float cc = fmaf(cosF,  cosU, -sSinF * sinU);

    // combine quadrant Q (sin/cos in {0,+-1})
    float sinC, cosC;
    if (q2)      { sinC = -sc;        cosC = -cc;        }
    else if (q1) { sinC = sgnt * cc;  cosC = -sgnt * sc; }
    else         { sinC = sc;         cosC = cc;         }

    // first-order phase-drift correction for reducing by f32(2pi)
    return fmaf(cosC, neff * DELTA_F, sinC);
}

__global__ void __launch_bounds__(256, 8) rope_dot_kernel(
    const float4* __restrict__ vec4,
    const float4* __restrict__ th4,
    const int*    __restrict__ m_ptr,
    float*        __restrict__ out,
    int n4)
{
    const float m = (float)(*m_ptr);
    float acc0 = 0.0f, acc1 = 0.0f;
    const int stride = gridDim.x * blockDim.x;

    #pragma unroll 4
    for (int i = blockIdx.x * blockDim.x + threadIdx.x; i < n4; i += stride) {
        float4 v = __ldg(&vec4[i]);
        float4 t = __ldg(&th4[i]);
        acc0 = fmaf(est_sin(t.x, m), v.x, acc0);
        acc1 = fmaf(est_sin(t.z, m), v.z, acc1);
    }
    float acc = acc0 + acc1;

    #pragma unroll
    for (int off = 16; off > 0; off >>= 1)
        acc += __shfl_down_sync(0xffffffffu, acc, off);

    __shared__ float sh[8];
    __shared__ bool  is_last;
    int lane = threadIdx.x & 31;
    int w    = threadIdx.x >> 5;
    if (lane == 0) sh[w] = acc;
    __syncthreads();
    if (threadIdx.x == 0) {
        float b = sh[0];
        #pragma unroll
        for (int k = 1; k < 8; k++) b += sh[k];
        g_partials[blockIdx.x] = b;
        __threadfence();
        unsigned tk = atomicAdd(&g_ticket, 1u);
        is_last = (tk == gridDim.x - 1);
    }
    __syncthreads();

    if (is_last) {
        double a = 0.0;
        for (int i = threadIdx.x; i < gridDim.x; i += blockDim.x)
            a += (double)g_partials[i];
        #pragma unroll
        for (int off = 16; off > 0; off >>= 1)
            a += __shfl_down_sync(0xffffffffu, a, off);
        __shared__ double shd[8];
        if (lane == 0) shd[w] = a;
        __syncthreads();
        if (threadIdx.x == 0) {
            double tot = shd[0];
            #pragma unroll
            for (int k = 1; k < 8; k++) tot += shd[k];
            out[0] = (float)(tot * (2.0 * (double)1.57f));
            g_ticket = 0;   // reset for next graph replay
        }
    }
}

extern "C" void kernel_launch(void* const* d_in, const int* in_sizes, int n_in,
                              void* d_out, int out_size) {
    const float4* vec4 = (const float4*)d_in[0];
    const float4* th4  = (const float4*)d_in[1];
    const int*    mptr = (const int*)d_in[2];

    int n  = in_sizes[0];
    int n4 = n / 4;

    const int threads = 256;
    const int blocks  = 1184;  // 148 SMs * 8 CTAs = 2048 threads/SM

    rope_dot_kernel<<<blocks, threads>>>(vec4, th4, mptr, (float*)d_out, n4);
}

// round 5
// speedup vs baseline: 2.4594x; 1.1480x over previous
#include <cuda_runtime.h>
#include <math.h>

// ---------------------------------------------------------------------------
// ROPE_64252710748794: out = ests @ vec + ests @ neg_swapped(vec)
//   = 2 * sum_k e_k * vec[2k],  e_k = 1.57*sin(C_k)  (theta pairs bitwise eq)
// est via discrete CORDIC rotations: exact-constant angle addition, no
// sinf/fmodf/FP64. Round 5: reg double-buffer pipeline @6 CTAs/SM + slimmer,
// pipe-balanced est (copysign / +-1 muls instead of select chains).
// ---------------------------------------------------------------------------

#define TWO_PI_F   6.283185307179586f
#define PI_F       3.141592653589793f
#define PI_12_F    1.5707963267948966f
#define PI_34_F    2.356194490192345f
#define PI_14_F    0.7853981633974483f
#define INV2PI_F   0.15915494309189535f
#define DELTA_F    1.7484556000744818e-7f   // f32(2pi) - 2pi

#define D3_5_F     0.061086523819801536f
#define D8_13_F    0.14189526818745917f
#define D26_565_F  0.46364671567952505f
#define D16_26_F   0.28379053637491834f
#define D36_87_F   0.64350289521467380f

#define SIN_F1_F   0.27999656988459544f
#define COS_F1_F   0.96000100046478220f
#define SIN_F2_F   0.60000142963530880f
#define COS_F2_F   0.79999892777837827f
#define SIN_U_F    0.12403445401859652f
#define COS_U_F    0.99227790841661646f

__device__ float        g_partials[4096];
__device__ unsigned int g_ticket;

// sin(theta - r), theta = m*th > 0 (m=4096, th>0).
__device__ __forceinline__ float est_sin(float theta) {
    // exact fmod(theta, 2pi_f32): single-rounding FMA + one-sided fixups
    float fn = floorf(theta * INV2PI_F);
    float t0 = fmaf(-fn, TWO_PI_F, theta);
    if (t0 < 0.0f)      { t0 += TWO_PI_F; fn -= 1.0f; }
    if (t0 >= TWO_PI_F) { t0 -= TWO_PI_F; fn += 1.0f; }

    // fold into (-pi, pi]
    bool  fold = t0 > PI_F;
    float t    = fold ? (t0 - TWO_PI_F) : t0;
    float neff = fold ? (fn + 1.0f)     : fn;

    // quadrant rotation (sgn only matters when |t|>pi/4 => t != 0)
    float at  = fabsf(t);
    bool  q2  = at > PI_34_F;
    bool  q1  = at > PI_14_F;
    float rot = q2 ? PI_F : (q1 ? PI_12_F : 0.0f);
    float r   = t - copysignf(rot, t);

    // friend rotation (sgn(r) matters only when |r| >= D8_13 => r != 0)
    float ar    = fabsf(r);
    bool  f2    = ar >= D26_565_F;
    bool  f1    = ar >= D8_13_F;
    float Fv    = f2 ? D36_87_F : (f1 ? D16_26_F : 0.0f);
    float sinFs = copysignf(f2 ? SIN_F2_F : (f1 ? SIN_F1_F : 0.0f), r); // s*sinF
    float cosF  = f2 ? COS_F2_F : (f1 ? COS_F1_F : 1.0f);
    float r2    = r - copysignf(Fv, r);

    // micro rotation (sgn(r2) matters only when |r2| >= 3.5deg => r2 != 0)
    bool  um   = fabsf(r2) >= D3_5_F;
    float sinU = um ? copysignf(SIN_U_F, r2) : 0.0f;
    float cosU = um ? COS_U_F                : 1.0f;

    // c = s*F + u
    float sc = fmaf(sinFs, cosU,  cosF * sinU);   // sin(c)
    float cc = fmaf(cosF,  cosU, -sinFs * sinU);  // cos(c) > 0 always

    // combine quadrant Q in {0, +-pi/2, +-pi} (exact +-1 muls, fma pipe)
    float sgnt = copysignf(1.0f, t);
    float sinC = q2 ? -sc : (q1 ?  sgnt * cc : sc);
    float cosC = q2 ? -cc : (q1 ? -sgnt * sc : cc);

    // first-order phase drift from reducing by f32(2pi) instead of 2pi
    return fmaf(cosC, neff * DELTA_F, sinC);
}

__global__ void __launch_bounds__(256, 6) rope_dot_kernel(
    const float4* __restrict__ vec4,
    const float4* __restrict__ th4,
    const int*    __restrict__ m_ptr,
    float*        __restrict__ out,
    int n4)
{
    const float m = (float)(*m_ptr);
    const int stride = gridDim.x * blockDim.x;
    float acc0 = 0.0f, acc1 = 0.0f;

    int i = blockIdx.x * blockDim.x + threadIdx.x;
    float4 v, t;
    if (i < n4) { v = __ldg(&vec4[i]); t = __ldg(&th4[i]); }

    while (i < n4) {
        int j = i + stride;
        float4 vn, tn;
        if (j < n4) { vn = __ldg(&vec4[j]); tn = __ldg(&th4[j]); }
        // pairs (4i,4i+1), (4i+2,4i+3): est identical within a pair
        acc0 = fmaf(est_sin(m * t.x), v.x, acc0);
        acc1 = fmaf(est_sin(m * t.z), v.z, acc1);
        v = vn; t = tn; i = j;
    }
    float acc = acc0 + acc1;

    #pragma unroll
    for (int off = 16; off > 0; off >>= 1)
        acc += __shfl_down_sync(0xffffffffu, acc, off);

    __shared__ float sh[8];
    __shared__ bool  is_last;
    int lane = threadIdx.x & 31;
    int w    = threadIdx.x >> 5;
    if (lane == 0) sh[w] = acc;
    __syncthreads();
    if (threadIdx.x == 0) {
        float b = sh[0];
        #pragma unroll
        for (int k = 1; k < 8; k++) b += sh[k];
        g_partials[blockIdx.x] = b;
        __threadfence();
        unsigned tk = atomicAdd(&g_ticket, 1u);
        is_last = (tk == gridDim.x - 1);
    }
    __syncthreads();

    if (is_last) {
        double a = 0.0;
        for (int k = threadIdx.x; k < gridDim.x; k += blockDim.x)
            a += (double)g_partials[k];
        #pragma unroll
        for (int off = 16; off > 0; off >>= 1)
            a += __shfl_down_sync(0xffffffffu, a, off);
        __shared__ double shd[8];
        if (lane == 0) shd[w] = a;
        __syncthreads();
        if (threadIdx.x == 0) {
            double tot = shd[0];
            #pragma unroll
            for (int k = 1; k < 8; k++) tot += shd[k];
            out[0] = (float)(tot * (2.0 * (double)1.57f));
            g_ticket = 0;   // reset for next graph replay
        }
    }
}

extern "C" void kernel_launch(void* const* d_in, const int* in_sizes, int n_in,
                              void* d_out, int out_size) {
    const float4* vec4 = (const float4*)d_in[0];
    const float4* th4  = (const float4*)d_in[1];
    const int*    mptr = (const int*)d_in[2];

    int n  = in_sizes[0];
    int n4 = n / 4;

    const int threads = 256;
    const int blocks  = 888;   // 148 SMs * 6 CTAs, ~40-reg budget for MLP

    rope_dot_kernel<<<blocks, threads>>>(vec4, th4, mptr, (float*)d_out, n4);
}